// round 1
// baseline (speedup 1.0000x reference)
#include <cuda_runtime.h>

// Problem constants (fixed shapes from reference setup_inputs)
#define TLEN 2048
#define BSZ  512
#define HD   64
#define G4   256      // 4*H gates
#define BPB  4        // batch rows per block
#define NTHREADS 256
#define NBLOCKS (BSZ / BPB)   // 128

// Shared memory layout (in floats)
//   WT0   [64][256]   w_hh0 transposed                 @ 0       (16384)
//   WT1   [128][256]  [w_ih1; w_hh1] transposed        @ 16384   (32768)
//   bs0   [256]       b_ih0 + b_hh0                    @ 49152
//   bs1   [256]       b_ih1 + b_hh1                    @ 49408
//   wi0   [256]       w_ih0 (column vector)            @ 49664
//   h1s   [4][64]                                      @ 49920
//   h2s   [4][64]                                      @ 50176
//   gbuf  [4][256]    gate pre-activations             @ 50432
//   ms    [4][128]    fc1 activations (head)           @ 51456
// total = 51968 floats = 207,872 bytes
#define SMEM_FLOATS 51968

__device__ __forceinline__ float sigm_f(float v) {
    return __fdividef(1.0f, 1.0f + __expf(-v));
}
__device__ __forceinline__ float tanh_f(float v) {
    // tanh(x) = 2*sigmoid(2x) - 1, via fast EX2/RCP (≈2 ulp)
    return fmaf(2.0f, __fdividef(1.0f, 1.0f + __expf(-2.0f * v)), -1.0f);
}

__global__ __launch_bounds__(NTHREADS, 1)
void lstm2_persistent_kernel(
    const float* __restrict__ x,      // [B, T]
    const float* __restrict__ w_ih0,  // [256, 1]
    const float* __restrict__ w_hh0,  // [256, 64]
    const float* __restrict__ b_ih0,  // [256]
    const float* __restrict__ b_hh0,  // [256]
    const float* __restrict__ w_ih1,  // [256, 64]
    const float* __restrict__ w_hh1,  // [256, 64]
    const float* __restrict__ b_ih1,  // [256]
    const float* __restrict__ b_hh1,  // [256]
    const float* __restrict__ fc1_w,  // [128, 64]
    const float* __restrict__ fc1_b,  // [128]
    const float* __restrict__ fc2_w,  // [10, 128]
    const float* __restrict__ fc2_b,  // [10]
    float* __restrict__ out)          // [B, 10]
{
    extern __shared__ float sm[];
    float* WT0  = sm;
    float* WT1  = sm + 16384;
    float* bs0  = sm + 49152;
    float* bs1  = sm + 49408;
    float* wi0  = sm + 49664;
    float* h1s  = sm + 49920;
    float* h2s  = sm + 50176;
    float* gbuf = sm + 50432;
    float* ms   = sm + 51456;

    const int tid   = threadIdx.x;
    const int l     = tid & 31;         // lane
    const int j     = tid;              // gate index handled by this thread in GEMV phases
                                        // (warp w covers gates [32w, 32w+32), lanes consecutive)
    const int bbase = blockIdx.x * BPB;

    // ---- Load weights (transposed) + fused biases into SMEM ----
    for (int i = tid; i < G4 * HD; i += NTHREADS) {
        int jj = i >> 6;      // gate row in global [256][64]
        int dd = i & 63;      // hidden index
        float v0 = w_hh0[i];
        float v1 = w_ih1[i];
        float v2 = w_hh1[i];
        WT0[dd * G4 + jj]        = v0;
        WT1[dd * G4 + jj]        = v1;
        WT1[(64 + dd) * G4 + jj] = v2;
    }
    for (int i = tid; i < G4; i += NTHREADS) {
        bs0[i] = b_ih0[i] + b_hh0[i];
        bs1[i] = b_ih1[i] + b_hh1[i];
        wi0[i] = w_ih0[i];
    }
    for (int i = tid; i < BPB * HD; i += NTHREADS) {
        h1s[i] = 0.0f;
        h2s[i] = 0.0f;
    }
    __syncthreads();

    // Per-thread cell state for the (b,u) pair this thread owns in pointwise phases
    const int pb = tid >> 6;       // batch within block (0..3)
    const int pu = tid & 63;       // hidden unit (0..63)
    float c1 = 0.0f, c2 = 0.0f;

    const float bj0 = bs0[j];
    const float bj1 = bs1[j];
    const float wj0 = wi0[j];

    for (int t = 0; t < TLEN; ++t) {
        // ---- fetch x[b][t] for the 4 batch rows (lane 0..3 load, broadcast via shfl) ----
        float xtmp = 0.0f;
        if (l < BPB) xtmp = x[(bbase + l) * TLEN + t];
        float xv0 = __shfl_sync(0xffffffffu, xtmp, 0);
        float xv1 = __shfl_sync(0xffffffffu, xtmp, 1);
        float xv2 = __shfl_sync(0xffffffffu, xtmp, 2);
        float xv3 = __shfl_sync(0xffffffffu, xtmp, 3);

        // ================= Phase A: layer-1 gate GEMV =================
        float a0 = 0.0f, a1 = 0.0f, a2 = 0.0f, a3 = 0.0f;
        #pragma unroll
        for (int d4 = 0; d4 < HD; d4 += 4) {
            float4 hb0 = *(const float4*)&h1s[0 * HD + d4];
            float4 hb1 = *(const float4*)&h1s[1 * HD + d4];
            float4 hb2 = *(const float4*)&h1s[2 * HD + d4];
            float4 hb3 = *(const float4*)&h1s[3 * HD + d4];
            const float* wrow = &WT0[d4 * G4 + j];
            #pragma unroll
            for (int dd = 0; dd < 4; ++dd) {
                float wv = wrow[dd * G4];
                float h0 = (&hb0.x)[dd];
                float h1 = (&hb1.x)[dd];
                float h2 = (&hb2.x)[dd];
                float h3 = (&hb3.x)[dd];
                a0 = fmaf(wv, h0, a0);
                a1 = fmaf(wv, h1, a1);
                a2 = fmaf(wv, h2, a2);
                a3 = fmaf(wv, h3, a3);
            }
        }
        a0 += bj0 + wj0 * xv0;
        a1 += bj0 + wj0 * xv1;
        a2 += bj0 + wj0 * xv2;
        a3 += bj0 + wj0 * xv3;
        gbuf[0 * G4 + j] = a0;
        gbuf[1 * G4 + j] = a1;
        gbuf[2 * G4 + j] = a2;
        gbuf[3 * G4 + j] = a3;
        __syncthreads();

        // ================= Phase B: layer-1 pointwise =================
        {
            const float* gb = &gbuf[pb * G4];
            float gi = gb[pu];
            float gf = gb[64 + pu];
            float gg = gb[128 + pu];
            float go = gb[192 + pu];
            float iv = sigm_f(gi);
            float fv = sigm_f(gf);
            float gv = tanh_f(gg);
            float ov = sigm_f(go);
            c1 = fmaf(fv, c1, iv * gv);
            h1s[pb * HD + pu] = ov * tanh_f(c1);
        }
        __syncthreads();

        // ================= Phase C: layer-2 gate GEMV (K = 128: [h1; h2]) =================
        a0 = bj1; a1 = bj1; a2 = bj1; a3 = bj1;
        #pragma unroll
        for (int d4 = 0; d4 < HD; d4 += 4) {
            float4 hb0 = *(const float4*)&h1s[0 * HD + d4];
            float4 hb1 = *(const float4*)&h1s[1 * HD + d4];
            float4 hb2 = *(const float4*)&h1s[2 * HD + d4];
            float4 hb3 = *(const float4*)&h1s[3 * HD + d4];
            const float* wrow = &WT1[d4 * G4 + j];
            #pragma unroll
            for (int dd = 0; dd < 4; ++dd) {
                float wv = wrow[dd * G4];
                a0 = fmaf(wv, (&hb0.x)[dd], a0);
                a1 = fmaf(wv, (&hb1.x)[dd], a1);
                a2 = fmaf(wv, (&hb2.x)[dd], a2);
                a3 = fmaf(wv, (&hb3.x)[dd], a3);
            }
        }
        #pragma unroll
        for (int d4 = 0; d4 < HD; d4 += 4) {
            float4 hb0 = *(const float4*)&h2s[0 * HD + d4];
            float4 hb1 = *(const float4*)&h2s[1 * HD + d4];
            float4 hb2 = *(const float4*)&h2s[2 * HD + d4];
            float4 hb3 = *(const float4*)&h2s[3 * HD + d4];
            const float* wrow = &WT1[(64 + d4) * G4 + j];
            #pragma unroll
            for (int dd = 0; dd < 4; ++dd) {
                float wv = wrow[dd * G4];
                a0 = fmaf(wv, (&hb0.x)[dd], a0);
                a1 = fmaf(wv, (&hb1.x)[dd], a1);
                a2 = fmaf(wv, (&hb2.x)[dd], a2);
                a3 = fmaf(wv, (&hb3.x)[dd], a3);
            }
        }
        gbuf[0 * G4 + j] = a0;
        gbuf[1 * G4 + j] = a1;
        gbuf[2 * G4 + j] = a2;
        gbuf[3 * G4 + j] = a3;
        __syncthreads();

        // ================= Phase D: layer-2 pointwise =================
        {
            const float* gb = &gbuf[pb * G4];
            float gi = gb[pu];
            float gf = gb[64 + pu];
            float gg = gb[128 + pu];
            float go = gb[192 + pu];
            float iv = sigm_f(gi);
            float fv = sigm_f(gf);
            float gv = tanh_f(gg);
            float ov = sigm_f(go);
            c2 = fmaf(fv, c2, iv * gv);
            h2s[pb * HD + pu] = ov * tanh_f(c2);
        }
        __syncthreads();
    }

    // ================= Head: y = relu(hT @ fc1.T + b1) @ fc2.T + b2 =================
    // fc1: 4 batches x 128 outs = 512 dots of length 64
    for (int i = tid; i < BPB * 128; i += NTHREADS) {
        int b = i >> 7;
        int n = i & 127;
        float acc = fc1_b[n];
        const float* wr = &fc1_w[n * HD];
        const float* hr = &h2s[b * HD];
        #pragma unroll
        for (int d = 0; d < HD; ++d) acc = fmaf(wr[d], hr[d], acc);
        ms[i] = fmaxf(acc, 0.0f);
    }
    __syncthreads();
    // fc2: 4 batches x 10 outs = 40 dots of length 128
    for (int i = tid; i < BPB * 10; i += NTHREADS) {
        int b = i / 10;
        int n = i - b * 10;
        float acc = fc2_b[n];
        const float* wr = &fc2_w[n * 128];
        const float* mr = &ms[b * 128];
        #pragma unroll
        for (int k = 0; k < 128; ++k) acc = fmaf(wr[k], mr[k], acc);
        out[(bbase + b) * 10 + n] = acc;
    }
}

extern "C" void kernel_launch(void* const* d_in, const int* in_sizes, int n_in,
                              void* d_out, int out_size)
{
    const float* x     = (const float*)d_in[0];
    const float* w_ih0 = (const float*)d_in[1];
    const float* w_hh0 = (const float*)d_in[2];
    const float* b_ih0 = (const float*)d_in[3];
    const float* b_hh0 = (const float*)d_in[4];
    const float* w_ih1 = (const float*)d_in[5];
    const float* w_hh1 = (const float*)d_in[6];
    const float* b_ih1 = (const float*)d_in[7];
    const float* b_hh1 = (const float*)d_in[8];
    const float* fc1_w = (const float*)d_in[9];
    const float* fc1_b = (const float*)d_in[10];
    const float* fc2_w = (const float*)d_in[11];
    const float* fc2_b = (const float*)d_in[12];
    float* out = (float*)d_out;

    size_t smem = (size_t)SMEM_FLOATS * sizeof(float);
    cudaFuncSetAttribute(lstm2_persistent_kernel,
                         cudaFuncAttributeMaxDynamicSharedMemorySize, (int)smem);
    lstm2_persistent_kernel<<<NBLOCKS, NTHREADS, smem>>>(
        x, w_ih0, w_hh0, b_ih0, b_hh0,
        w_ih1, w_hh1, b_ih1, b_hh1,
        fc1_w, fc1_b, fc2_w, fc2_b, out);
}